// round 1
// baseline (speedup 1.0000x reference)
#include <cuda_runtime.h>
#include <math.h>

#define HW   4096
#define NB   4
#define CIN  256
#define CK   64
#define CV   256
#define BQ   64
#define BK   64

// Scratch (device globals: no allocation inside kernel_launch)
__device__ float g_kbuf[NB * CK * HW];   // [b][ck][t]   4 MB  (channel-major)
__device__ float g_vbuf[NB * HW * CV];   // [b][t][cv]  16 MB  (token-major)

// ---------------------------------------------------------------------------
// Projection: out[ko][t] = sum_c W[ko][c] * x[b][c][t] + bias[ko], optional BN
// Tile: 64 ko x 64 t per CTA, K-loop over CIN in chunks of 64.
// ---------------------------------------------------------------------------
__global__ __launch_bounds__(256) void proj_kernel(
    const float* __restrict__ x, const float* __restrict__ W,
    const float* __restrict__ bias,
    const float* __restrict__ bn_gamma, const float* __restrict__ bn_beta,
    const float* __restrict__ bn_mean,  const float* __restrict__ bn_var,
    int is_k)
{
    __shared__ float xs[64][64];   // [c][t]
    __shared__ float ws[64][68];   // [c][ko]  (pad 4 keeps 16B alignment)

    const int t0  = blockIdx.x * 64;
    const int ko0 = blockIdx.y * 64;
    const int b   = blockIdx.z;
    const int tid = threadIdx.x;
    const int ti  = tid >> 4;    // ko sub-tile (0..15)
    const int tj  = tid & 15;    // t  sub-tile (0..15)

    float acc[4][4] = {};

    for (int c0 = 0; c0 < CIN; c0 += 64) {
        // x tile: 64 c x 64 t, fully coalesced float4
        #pragma unroll
        for (int it = 0; it < 4; it++) {
            int v = tid + it * 256;
            int c = v >> 4, i4 = (v & 15) << 2;
            *(float4*)&xs[c][i4] =
                *(const float4*)&x[((size_t)(b * CIN + c0 + c)) * HW + t0 + i4];
        }
        // W tile transposed into [c][ko]
        #pragma unroll
        for (int it = 0; it < 4; it++) {
            int v = tid + it * 256;
            int ko = v >> 4, c4 = (v & 15) << 2;
            float4 w = *(const float4*)&W[(ko0 + ko) * CIN + c0 + c4];
            ws[c4 + 0][ko] = w.x; ws[c4 + 1][ko] = w.y;
            ws[c4 + 2][ko] = w.z; ws[c4 + 3][ko] = w.w;
        }
        __syncthreads();

        #pragma unroll 8
        for (int c = 0; c < 64; c++) {
            float4 wv = *(float4*)&ws[c][ti * 4];   // 4 ko values
            float4 xv = *(float4*)&xs[c][tj * 4];   // 4 t values
            float wr[4] = {wv.x, wv.y, wv.z, wv.w};
            float xr[4] = {xv.x, xv.y, xv.z, xv.w};
            #pragma unroll
            for (int ii = 0; ii < 4; ii++)
                #pragma unroll
                for (int jj = 0; jj < 4; jj++)
                    acc[ii][jj] = fmaf(wr[ii], xr[jj], acc[ii][jj]);
        }
        __syncthreads();
    }

    // Epilogue: bias (+ folded BN for K), then store
    if (is_k) {
        #pragma unroll
        for (int ii = 0; ii < 4; ii++) {
            int ko = ko0 + ti * 4 + ii;
            float inv = bn_gamma[ko] * rsqrtf(bn_var[ko] + 1e-5f);
            float add = bn_beta[ko] - bn_mean[ko] * inv;
            float bz  = bias[ko];
            float4 o;
            o.x = (acc[ii][0] + bz) * inv + add;
            o.y = (acc[ii][1] + bz) * inv + add;
            o.z = (acc[ii][2] + bz) * inv + add;
            o.w = (acc[ii][3] + bz) * inv + add;
            // channel-major: g_kbuf[b][ko][t]
            *(float4*)&g_kbuf[((size_t)(b * CK + ko)) * HW + t0 + tj * 4] = o;
        }
    } else {
        #pragma unroll
        for (int jj = 0; jj < 4; jj++) {
            int t = t0 + tj * 4 + jj;
            float4 o;
            o.x = acc[0][jj] + bias[ko0 + ti * 4 + 0];
            o.y = acc[1][jj] + bias[ko0 + ti * 4 + 1];
            o.z = acc[2][jj] + bias[ko0 + ti * 4 + 2];
            o.w = acc[3][jj] + bias[ko0 + ti * 4 + 3];
            // token-major: g_vbuf[b][t][ko]
            *(float4*)&g_vbuf[((size_t)(b * HW + t)) * CV + ko0 + ti * 4] = o;
        }
    }
}

// ---------------------------------------------------------------------------
// Flash attention (Q == K): per CTA one 64-query tile, loop over 64 key tiles.
// smem: Qs[c][i] 16KB | Ks[c][j] 16KB | Ps[j][i] pad68 17KB | Vs[j][c] 64KB
// ---------------------------------------------------------------------------
#define QS_OFF 0
#define KS_OFF (64 * 64)
#define PS_OFF (KS_OFF + 64 * 64)
#define VS_OFF (PS_OFF + 64 * 68)
#define SMEM_FLOATS (VS_OFF + 64 * 256)

__global__ __launch_bounds__(256, 1) void flash_kernel(float* __restrict__ out)
{
    extern __shared__ float smem[];
    float* Qs = smem + QS_OFF;
    float* Ks = smem + KS_OFF;
    float* Ps = smem + PS_OFF;   // [j][i], row stride 68
    float* Vs = smem + VS_OFF;   // [j][c], row stride 256

    const int q0  = blockIdx.x * BQ;
    const int b   = blockIdx.y;
    const int tid = threadIdx.x;
    const int ti  = tid >> 4;    // query-row group (4 rows)
    const int tj  = tid & 15;    // key-col group (4 cols) / channel group (16 ch)

    const float* kb = g_kbuf + (size_t)b * CK * HW;
    const float* vb = g_vbuf + (size_t)b * HW * CV;

    // Load Q tile: Qs[c][i] <- kb[c][q0+i]  (already channel-major, no transpose)
    #pragma unroll
    for (int it = 0; it < 4; it++) {
        int v = tid + it * 256;
        int c = v >> 4, i4 = (v & 15) << 2;
        *(float4*)&Qs[c * 64 + i4] = *(const float4*)&kb[(size_t)c * HW + q0 + i4];
    }

    float m[4], l[4], acc[4][16];
    #pragma unroll
    for (int ii = 0; ii < 4; ii++) { m[ii] = -1e30f; l[ii] = 0.0f; }
    #pragma unroll
    for (int ii = 0; ii < 4; ii++)
        #pragma unroll
        for (int cc = 0; cc < 16; cc++) acc[ii][cc] = 0.0f;

    for (int kt = 0; kt < HW / BK; kt++) {
        const int k0 = kt * BK;

        // Load K tile (16KB) and V tile (64KB), coalesced
        #pragma unroll
        for (int it = 0; it < 4; it++) {
            int v = tid + it * 256;
            int c = v >> 4, i4 = (v & 15) << 2;
            *(float4*)&Ks[c * 64 + i4] = *(const float4*)&kb[(size_t)c * HW + k0 + i4];
        }
        #pragma unroll
        for (int it = 0; it < 16; it++) {
            int v = tid + it * 256;            // float4 index: 64*256/4 = 4096
            int j = v >> 6, c4 = (v & 63) << 2;
            *(float4*)&Vs[j * 256 + c4] =
                *(const float4*)&vb[(size_t)(k0 + j) * CV + c4];
        }
        __syncthreads();

        // ---- S = Q^T K  (4x4 per thread) ----
        float s[4][4] = {};
        #pragma unroll 8
        for (int c = 0; c < 64; c++) {
            float4 qv = *(float4*)&Qs[c * 64 + ti * 4];
            float4 kv = *(float4*)&Ks[c * 64 + tj * 4];
            float qr[4] = {qv.x, qv.y, qv.z, qv.w};
            float kr[4] = {kv.x, kv.y, kv.z, kv.w};
            #pragma unroll
            for (int ii = 0; ii < 4; ii++)
                #pragma unroll
                for (int jj = 0; jj < 4; jj++)
                    s[ii][jj] = fmaf(qr[ii], kr[jj], s[ii][jj]);
        }

        // ---- online softmax over the 64-wide key tile ----
        float mt[4], rs[4], sc[4];
        #pragma unroll
        for (int ii = 0; ii < 4; ii++) {
            float v0 = fmaxf(fmaxf(s[ii][0], s[ii][1]), fmaxf(s[ii][2], s[ii][3]));
            #pragma unroll
            for (int off = 8; off >= 1; off >>= 1)
                v0 = fmaxf(v0, __shfl_xor_sync(0xffffffffu, v0, off, 16));
            mt[ii] = fmaxf(m[ii], v0);
        }
        #pragma unroll
        for (int ii = 0; ii < 4; ii++) {
            float r = 0.0f;
            #pragma unroll
            for (int jj = 0; jj < 4; jj++) {
                s[ii][jj] = __expf(s[ii][jj] - mt[ii]);
                r += s[ii][jj];
            }
            #pragma unroll
            for (int off = 8; off >= 1; off >>= 1)
                r += __shfl_xor_sync(0xffffffffu, r, off, 16);
            rs[ii] = r;
            sc[ii] = __expf(m[ii] - mt[ii]);
            l[ii]  = l[ii] * sc[ii] + rs[ii];
            m[ii]  = mt[ii];
        }
        // rescale accumulators
        #pragma unroll
        for (int ii = 0; ii < 4; ii++)
            #pragma unroll
            for (int cc = 0; cc < 16; cc++) acc[ii][cc] *= sc[ii];

        // write P transposed: Ps[j][i]
        #pragma unroll
        for (int jj = 0; jj < 4; jj++) {
            float4 pv = make_float4(s[0][jj], s[1][jj], s[2][jj], s[3][jj]);
            *(float4*)&Ps[(tj * 4 + jj) * 68 + ti * 4] = pv;
        }
        __syncthreads();

        // ---- acc += P * V  (rows i = 4*ti.., channels c = 16*tj..) ----
        #pragma unroll 2
        for (int j = 0; j < 64; j++) {
            float4 pv = *(float4*)&Ps[j * 68 + ti * 4];
            float pr[4] = {pv.x, pv.y, pv.z, pv.w};
            float4 va = *(float4*)&Vs[j * 256 + tj * 16 + 0];
            float4 vbv = *(float4*)&Vs[j * 256 + tj * 16 + 4];
            float4 vc = *(float4*)&Vs[j * 256 + tj * 16 + 8];
            float4 vd = *(float4*)&Vs[j * 256 + tj * 16 + 12];
            float vr[16] = {va.x, va.y, va.z, va.w, vbv.x, vbv.y, vbv.z, vbv.w,
                            vc.x, vc.y, vc.z, vc.w, vd.x, vd.y, vd.z, vd.w};
            #pragma unroll
            for (int ii = 0; ii < 4; ii++)
                #pragma unroll
                for (int cc = 0; cc < 16; cc++)
                    acc[ii][cc] = fmaf(pr[ii], vr[cc], acc[ii][cc]);
        }
        __syncthreads();
    }

    // ---- finalize: out[b][c][i] = acc[i][c] / l[i] ----
    float rinv[4];
    #pragma unroll
    for (int ii = 0; ii < 4; ii++) rinv[ii] = 1.0f / l[ii];
    #pragma unroll
    for (int cc = 0; cc < 16; cc++) {
        int c = tj * 16 + cc;
        float4 o;
        o.x = acc[0][cc] * rinv[0];
        o.y = acc[1][cc] * rinv[1];
        o.z = acc[2][cc] * rinv[2];
        o.w = acc[3][cc] * rinv[3];
        *(float4*)&out[((size_t)(b * CV + c)) * HW + q0 + ti * 4] = o;
    }
}

// ---------------------------------------------------------------------------
extern "C" void kernel_launch(void* const* d_in, const int* in_sizes, int n_in,
                              void* d_out, int out_size)
{
    const float* x        = (const float*)d_in[0];
    const float* Wk       = (const float*)d_in[1];
    const float* bk       = (const float*)d_in[2];
    const float* bn_gamma = (const float*)d_in[3];
    const float* bn_beta  = (const float*)d_in[4];
    const float* bn_mean  = (const float*)d_in[5];
    const float* bn_var   = (const float*)d_in[6];
    const float* Wv       = (const float*)d_in[7];
    const float* bv       = (const float*)d_in[8];
    float* out = (float*)d_out;

    const int smem_bytes = SMEM_FLOATS * (int)sizeof(float);   // ~113 KB
    cudaFuncSetAttribute(flash_kernel,
                         cudaFuncAttributeMaxDynamicSharedMemorySize, smem_bytes);

    // K projection (with BN fold): grid (t-tiles, ko-tiles, batch)
    proj_kernel<<<dim3(HW / 64, CK / 64, NB), 256>>>(
        x, Wk, bk, bn_gamma, bn_beta, bn_mean, bn_var, 1);
    // V projection
    proj_kernel<<<dim3(HW / 64, CV / 64, NB), 256>>>(
        x, Wv, bv, nullptr, nullptr, nullptr, nullptr, 0);
    // Fused flash attention
    flash_kernel<<<dim3(HW / BQ, NB), 256, smem_bytes>>>(out);
}

// round 5
// speedup vs baseline: 5.9646x; 5.9646x over previous
#include <cuda_runtime.h>
#include <cuda_bf16.h>
#include <cstdint>
#include <math.h>

#define HW   4096
#define NB   4
#define CIN  256
#define CK   64
#define CV   256
#define BQ   128
#define BK   64
#define NKT  (HW / BK)

// ---------------- bf16 hi/lo split scratch (device globals) ----------------
__device__ __nv_bfloat16 g_k16h[NB * HW * CK];   // [b][t][d] token-major
__device__ __nv_bfloat16 g_k16l[NB * HW * CK];
__device__ __nv_bfloat16 g_v16h[NB * CV * HW];   // [b][c][t] channel-major
__device__ __nv_bfloat16 g_v16l[NB * CV * HW];

// ---------------- helpers ----------------
__device__ __forceinline__ uint32_t smem_u32(const void* p) {
    uint32_t a;
    asm("{ .reg .u64 t; cvta.to.shared.u64 t, %1; cvt.u32.u64 %0, t; }" : "=r"(a) : "l"(p));
    return a;
}
__device__ __forceinline__ void cp16(uint32_t dst, const void* src) {
    asm volatile("cp.async.cg.shared.global [%0], [%1], 16;" :: "r"(dst), "l"(src));
}
#define CP_COMMIT() asm volatile("cp.async.commit_group;" ::: "memory")
#define CP_WAIT0()  asm volatile("cp.async.wait_group 0;" ::: "memory")

__device__ __forceinline__ void ldsm4(uint32_t& r0, uint32_t& r1, uint32_t& r2, uint32_t& r3,
                                      uint32_t addr) {
    asm volatile("ldmatrix.sync.aligned.m8n8.x4.shared.b16 {%0,%1,%2,%3}, [%4];"
                 : "=r"(r0), "=r"(r1), "=r"(r2), "=r"(r3) : "r"(addr));
}
__device__ __forceinline__ void mma16816(float (&d)[4],
                                         uint32_t a0, uint32_t a1, uint32_t a2, uint32_t a3,
                                         uint32_t b0, uint32_t b1) {
    asm volatile("mma.sync.aligned.m16n8k16.row.col.f32.bf16.bf16.f32 "
                 "{%0,%1,%2,%3}, {%4,%5,%6,%7}, {%8,%9}, {%0,%1,%2,%3};"
                 : "+f"(d[0]), "+f"(d[1]), "+f"(d[2]), "+f"(d[3])
                 : "r"(a0), "r"(a1), "r"(a2), "r"(a3), "r"(b0), "r"(b1));
}

__device__ __forceinline__ void bsplit(float x, __nv_bfloat16& h, __nv_bfloat16& l) {
    h = __float2bfloat16(x);
    l = __float2bfloat16(x - __bfloat162float(h));
}
__device__ __forceinline__ uint32_t pack2(__nv_bfloat16 a, __nv_bfloat16 b) {
    __nv_bfloat162 t(a, b);
    return *reinterpret_cast<uint32_t*>(&t);
}
// pack hi parts of two floats into one bf16x2 reg
__device__ __forceinline__ uint32_t packhi(float x, float y) {
    return pack2(__float2bfloat16(x), __float2bfloat16(y));
}
__device__ __forceinline__ uint32_t packlo(float x, float y) {
    __nv_bfloat16 hx = __float2bfloat16(x), hy = __float2bfloat16(y);
    return pack2(__float2bfloat16(x - __bfloat162float(hx)),
                 __float2bfloat16(y - __bfloat162float(hy)));
}

// ---------------- smem layout (bytes); row pitch 144B (72 halves) -------------
#define PITCH  144
#define QH_OFF 0
#define QL_OFF 18432
#define KBASE  36864                       // K: [stage][hi/lo] 64 rows x 144B = 9216
#define KH(st) (KBASE + (st) * 9216)
#define KL(st) (KBASE + 18432 + (st) * 9216)
#define VBASE  (KBASE + 36864)             // V: [stage][hi/lo] 256 rows x 144B = 36864
#define VH(st) (VBASE + (st) * 36864)
#define VL(st) (VBASE + 73728 + (st) * 36864)
#define SMEM_TOTAL (VBASE + 147456)        // 221184 B
#define OS_OFF 36864                       // O staging reuses K/V region: 256 x 132 f32
#define OPITCH 132

// ---------------------------------------------------------------------------
// Projection (fp32 FFMA GEMM) -> bf16 hi/lo split outputs
// ---------------------------------------------------------------------------
__global__ __launch_bounds__(256) void proj_kernel(
    const float* __restrict__ x, const float* __restrict__ W,
    const float* __restrict__ bias,
    const float* __restrict__ bn_gamma, const float* __restrict__ bn_beta,
    const float* __restrict__ bn_mean,  const float* __restrict__ bn_var,
    int is_k)
{
    __shared__ float xs[64][64];
    __shared__ float ws[64][68];

    const int t0  = blockIdx.x * 64;
    const int ko0 = blockIdx.y * 64;
    const int b   = blockIdx.z;
    const int tid = threadIdx.x;
    const int ti  = tid >> 4;
    const int tj  = tid & 15;

    float acc[4][4] = {};

    for (int c0 = 0; c0 < CIN; c0 += 64) {
        #pragma unroll
        for (int it = 0; it < 4; it++) {
            int v = tid + it * 256;
            int c = v >> 4, i4 = (v & 15) << 2;
            *(float4*)&xs[c][i4] =
                *(const float4*)&x[((size_t)(b * CIN + c0 + c)) * HW + t0 + i4];
        }
        #pragma unroll
        for (int it = 0; it < 4; it++) {
            int v = tid + it * 256;
            int ko = v >> 4, c4 = (v & 15) << 2;
            float4 w = *(const float4*)&W[(ko0 + ko) * CIN + c0 + c4];
            ws[c4 + 0][ko] = w.x; ws[c4 + 1][ko] = w.y;
            ws[c4 + 2][ko] = w.z; ws[c4 + 3][ko] = w.w;
        }
        __syncthreads();

        #pragma unroll 8
        for (int c = 0; c < 64; c++) {
            float4 wv = *(float4*)&ws[c][ti * 4];
            float4 xv = *(float4*)&xs[c][tj * 4];
            float wr[4] = {wv.x, wv.y, wv.z, wv.w};
            float xr[4] = {xv.x, xv.y, xv.z, xv.w};
            #pragma unroll
            for (int ii = 0; ii < 4; ii++)
                #pragma unroll
                for (int jj = 0; jj < 4; jj++)
                    acc[ii][jj] = fmaf(wr[ii], xr[jj], acc[ii][jj]);
        }
        __syncthreads();
    }

    if (is_k) {
        float kv[4][4];
        #pragma unroll
        for (int ii = 0; ii < 4; ii++) {
            int ko = ko0 + ti * 4 + ii;
            float inv = bn_gamma[ko] * rsqrtf(bn_var[ko] + 1e-5f);
            float add = bn_beta[ko] - bn_mean[ko] * inv;
            float bz  = bias[ko];
            #pragma unroll
            for (int jj = 0; jj < 4; jj++)
                kv[jj][ii] = (acc[ii][jj] + bz) * inv + add;
        }
        #pragma unroll
        for (int jj = 0; jj < 4; jj++) {
            int t = t0 + tj * 4 + jj;
            __nv_bfloat16 h[4], l[4];
            #pragma unroll
            for (int ii = 0; ii < 4; ii++) bsplit(kv[jj][ii], h[ii], l[ii]);
            size_t base = ((size_t)(b * HW + t)) * CK + ko0 + ti * 4;
            *(uint32_t*)&g_k16h[base]     = pack2(h[0], h[1]);
            *(uint32_t*)&g_k16h[base + 2] = pack2(h[2], h[3]);
            *(uint32_t*)&g_k16l[base]     = pack2(l[0], l[1]);
            *(uint32_t*)&g_k16l[base + 2] = pack2(l[2], l[3]);
        }
    } else {
        #pragma unroll
        for (int ii = 0; ii < 4; ii++) {
            int c = ko0 + ti * 4 + ii;
            float bz = bias[c];
            __nv_bfloat16 h[4], l[4];
            #pragma unroll
            for (int jj = 0; jj < 4; jj++) bsplit(acc[ii][jj] + bz, h[jj], l[jj]);
            size_t base = ((size_t)(b * CV + c)) * HW + t0 + tj * 4;
            *(uint32_t*)&g_v16h[base]     = pack2(h[0], h[1]);
            *(uint32_t*)&g_v16h[base + 2] = pack2(h[2], h[3]);
            *(uint32_t*)&g_v16l[base]     = pack2(l[0], l[1]);
            *(uint32_t*)&g_v16l[base + 2] = pack2(l[2], l[3]);
        }
    }
}

// ---------------------------------------------------------------------------
// K+V tile stage loader (cp.async). K: 64x64 halves; V: 256x64 halves.
// ---------------------------------------------------------------------------
__device__ __forceinline__ void load_kv(uint32_t sb, int st,
    const __nv_bfloat16* kh, const __nv_bfloat16* kl,
    const __nv_bfloat16* vh, const __nv_bfloat16* vl, int j0, int tid)
{
    #pragma unroll
    for (int it = 0; it < 2; it++) {
        int idx = tid + it * 256;          // 512 chunks
        int r = idx >> 3, ck = idx & 7;
        uint32_t d = r * PITCH + ck * 16;
        const char* sh = (const char*)(kh + (size_t)(j0 + r) * CK) + ck * 16;
        const char* sl = (const char*)(kl + (size_t)(j0 + r) * CK) + ck * 16;
        cp16(sb + KH(st) + d, sh);
        cp16(sb + KL(st) + d, sl);
    }
    #pragma unroll
    for (int it = 0; it < 8; it++) {
        int idx = tid + it * 256;          // 2048 chunks
        int r = idx >> 3, ck = idx & 7;    // r = channel row 0..255
        uint32_t d = r * PITCH + ck * 16;
        const char* sh = (const char*)(vh + (size_t)r * HW + j0) + ck * 16;
        const char* sl = (const char*)(vl + (size_t)r * HW + j0) + ck * 16;
        cp16(sb + VH(st) + d, sh);
        cp16(sb + VL(st) + d, sl);
    }
}

// ---------------------------------------------------------------------------
// HMMA flash attention: 8 warps, warp owns 16 query rows x all 256 channels.
// bf16 hi/lo split: 3 MMAs per logical GEMM.
// ---------------------------------------------------------------------------
__global__ __launch_bounds__(256, 1) void flashm_kernel(float* __restrict__ out)
{
    extern __shared__ char smem[];
    const uint32_t sb = smem_u32(smem);
    const int tid  = threadIdx.x;
    const int w    = tid >> 5;
    const int lane = tid & 31;
    const int g    = lane >> 2;       // row within 8
    const int tig  = lane & 3;        // col pair selector
    const int i0   = w * 16;          // warp's query-row base within tile

    const int q0 = blockIdx.x * BQ;
    const int b  = blockIdx.y;

    const __nv_bfloat16* kh = g_k16h + (size_t)b * HW * CK;
    const __nv_bfloat16* kl = g_k16l + (size_t)b * HW * CK;
    const __nv_bfloat16* vh = g_v16h + (size_t)b * CV * HW;
    const __nv_bfloat16* vl = g_v16l + (size_t)b * CV * HW;

    // Q tiles (persistent): 128 rows x 64 halves, hi+lo
    #pragma unroll
    for (int it = 0; it < 4; it++) {
        int idx = tid + it * 256;          // 1024 chunks per buffer
        int r = idx >> 3, ck = idx & 7;
        uint32_t d = r * PITCH + ck * 16;
        cp16(sb + QH_OFF + d, (const char*)(kh + (size_t)(q0 + r) * CK) + ck * 16);
        cp16(sb + QL_OFF + d, (const char*)(kl + (size_t)(q0 + r) * CK) + ck * 16);
    }
    load_kv(sb, 0, kh, kl, vh, vl, 0, tid);
    CP_COMMIT();

    float m0 = -1e30f, m1 = -1e30f, l0 = 0.0f, l1 = 0.0f;
    float O[32][4];
    #pragma unroll
    for (int t = 0; t < 32; t++)
        #pragma unroll
        for (int r = 0; r < 4; r++) O[t][r] = 0.0f;

    // ldmatrix per-lane address components
    const uint32_t a_row = (uint32_t)(lane & 15);            // + i0
    const uint32_t a_col = (uint32_t)((lane & 16) >> 1);     // 0 or 8 (halves)
    const uint32_t b_row = (uint32_t)((lane & 7) + ((lane & 16) >> 1));
    const uint32_t b_col = (uint32_t)(lane & 8);             // 0 or 8 (halves)

    for (int kt = 0; kt < NKT; kt++) {
        const int st = kt & 1;
        CP_WAIT0();
        __syncthreads();
        if (kt + 1 < NKT) load_kv(sb, st ^ 1, kh, kl, vh, vl, (kt + 1) * BK, tid);
        CP_COMMIT();

        // ---------------- S = Q K^T (16 x 64), 3-way split ----------------
        float S[8][4];
        #pragma unroll
        for (int t = 0; t < 8; t++)
            #pragma unroll
            for (int r = 0; r < 4; r++) S[t][r] = 0.0f;

        #pragma unroll
        for (int kk = 0; kk < 4; kk++) {
            uint32_t qoff = (i0 + a_row) * PITCH + (kk * 16 + a_col) * 2;
            uint32_t aH0, aH1, aH2, aH3, aL0, aL1, aL2, aL3;
            ldsm4(aH0, aH1, aH2, aH3, sb + QH_OFF + qoff);
            ldsm4(aL0, aL1, aL2, aL3, sb + QL_OFF + qoff);
            #pragma unroll
            for (int p = 0; p < 4; p++) {
                uint32_t koff = (p * 16 + b_row) * PITCH + (kk * 16 + b_col) * 2;
                uint32_t bH0, bH1, bH2, bH3, bL0, bL1, bL2, bL3;
                ldsm4(bH0, bH1, bH2, bH3, sb + KH(st) + koff);
                ldsm4(bL0, bL1, bL2, bL3, sb + KL(st) + koff);
                mma16816(S[2*p],   aH0, aH1, aH2, aH3, bH0, bH1);
                mma16816(S[2*p],   aH0, aH1, aH2, aH3, bL0, bL1);
                mma16816(S[2*p],   aL0, aL1, aL2, aL3, bH0, bH1);
                mma16816(S[2*p+1], aH0, aH1, aH2, aH3, bH2, bH3);
                mma16816(S[2*p+1], aH0, aH1, aH2, aH3, bL2, bL3);
                mma16816(S[2*p+1], aL0, aL1, aL2, aL3, bH2, bH3);
            }
        }

        // ---------------- online softmax (rows g and g+8) ----------------
        float mx0 = -1e30f, mx1 = -1e30f;
        #pragma unroll
        for (int t = 0; t < 8; t++) {
            mx0 = fmaxf(mx0, fmaxf(S[t][0], S[t][1]));
            mx1 = fmaxf(mx1, fmaxf(S[t][2], S[t][3]));
        }
        mx0 = fmaxf(mx0, __shfl_xor_sync(0xffffffffu, mx0, 1));
        mx0 = fmaxf(mx0, __shfl_xor_sync(0xffffffffu, mx0, 2));
        mx1 = fmaxf(mx1, __shfl_xor_sync(0xffffffffu, mx1, 1));
        mx1 = fmaxf(mx1, __shfl_xor_sync(0xffffffffu, mx1, 2));
        mx0 = fmaxf(mx0, m0);
        mx1 = fmaxf(mx1, m1);
        const float sc0 = __expf(m0 - mx0);
        const float sc1 = __expf(m1 - mx1);
        m0 = mx0; m1 = mx1;

        float r0 = 0.0f, r1 = 0.0f;
        #pragma unroll
        for (int t = 0; t < 8; t++) {
            S[t][0] = __expf(S[t][0] - mx0);
            S[t][1] = __expf(S[t][1] - mx0);
            S[t][2] = __expf(S[t][2] - mx1);
            S[t][3] = __expf(S[t][3] - mx1);
            r0 += S[t][0] + S[t][1];
            r1 += S[t][2] + S[t][3];
        }
        r0 += __shfl_xor_sync(0xffffffffu, r0, 1);
        r0 += __shfl_xor_sync(0xffffffffu, r0, 2);
        r1 += __shfl_xor_sync(0xffffffffu, r1, 1);
        r1 += __shfl_xor_sync(0xffffffffu, r1, 2);
        l0 = l0 * sc0 + r0;
        l1 = l1 * sc1 + r1;

        // rescale O
        #pragma unroll
        for (int t = 0; t < 32; t++) {
            O[t][0] *= sc0; O[t][1] *= sc0;
            O[t][2] *= sc1; O[t][3] *= sc1;
        }

        // ---------------- P repack (f32 -> bf16 hi/lo A frags) ----------------
        uint32_t Ph[4][4], Pl[4][4];
        #pragma unroll
        for (int kk = 0; kk < 4; kk++) {
            Ph[kk][0] = packhi(S[2*kk][0],   S[2*kk][1]);
            Ph[kk][1] = packhi(S[2*kk][2],   S[2*kk][3]);
            Ph[kk][2] = packhi(S[2*kk+1][0], S[2*kk+1][1]);
            Ph[kk][3] = packhi(S[2*kk+1][2], S[2*kk+1][3]);
            Pl[kk][0] = packlo(S[2*kk][0],   S[2*kk][1]);
            Pl[kk][1] = packlo(S[2*kk][2],   S[2*kk][3]);
            Pl[kk][2] = packlo(S[2*kk+1][0], S[2*kk+1][1]);
            Pl[kk][3] = packlo(S[2*kk+1][2], S[2*kk+1][3]);
        }

        // ---------------- O += P V  (16 x 256), 3-way split ----------------
        #pragma unroll
        for (int kk = 0; kk < 4; kk++) {
            #pragma unroll
            for (int p = 0; p < 16; p++) {
                uint32_t voff = (p * 16 + b_row) * PITCH + (kk * 16 + b_col) * 2;
                uint32_t vH0, vH1, vH2, vH3, vL0, vL1, vL2, vL3;
                ldsm4(vH0, vH1, vH2, vH3, sb + VH(st) + voff);
                ldsm4(vL0, vL1, vL2, vL3, sb + VL(st) + voff);
                mma16816(O[2*p],   Ph[kk][0], Ph[kk][1], Ph[kk][2], Ph[kk][3], vH0, vH1);
                mma16816(O[2*p],   Pl[kk][0], Pl[kk][1], Pl[kk][2], Pl[kk][3], vH0, vH1);
                mma16816(O[2*p],   Ph[kk][0], Ph[kk][1], Ph[kk][2], Ph[kk][3], vL0, vL1);
                mma16816(O[2*p+1], Ph[kk][0], Ph[kk][1], Ph[kk][2], Ph[kk][3], vH2, vH3);
                mma16816(O[2*p+1], Pl[kk][0], Pl[kk][1], Pl[kk][2], Pl[kk][3], vH2, vH3);
                mma16816(O[2*p+1], Ph[kk][0], Ph[kk][1], Ph[kk][2], Ph[kk][3], vL2, vL3);
            }
        }
    }

    // ---------------- epilogue: stage O in smem, coalesced store ----------------
    __syncthreads();    // tile buffers dead; reuse region for O staging
    {
        float* os = (float*)(smem + OS_OFF);
        const float il0 = 1.0f / l0;
        const float il1 = 1.0f / l1;
        #pragma unroll
        for (int t = 0; t < 32; t++) {
            int c = t * 8 + tig * 2;
            os[(c    ) * OPITCH + i0 + g    ] = O[t][0] * il0;
            os[(c + 1) * OPITCH + i0 + g    ] = O[t][1] * il0;
            os[(c    ) * OPITCH + i0 + g + 8] = O[t][2] * il1;
            os[(c + 1) * OPITCH + i0 + g + 8] = O[t][3] * il1;
        }
        __syncthreads();
        #pragma unroll
        for (int cc = 0; cc < 32; cc++) {
            int c = w * 32 + cc;
            float4 v = *(float4*)&os[c * OPITCH + lane * 4];
            *(float4*)&out[((size_t)(b * CV + c)) * HW + q0 + lane * 4] = v;
        }
    }
}

// ---------------------------------------------------------------------------
extern "C" void kernel_launch(void* const* d_in, const int* in_sizes, int n_in,
                              void* d_out, int out_size)
{
    const float* x        = (const float*)d_in[0];
    const float* Wk       = (const float*)d_in[1];
    const float* bk       = (const float*)d_in[2];
    const float* bn_gamma = (const float*)d_in[3];
    const float* bn_beta  = (const float*)d_in[4];
    const float* bn_mean  = (const float*)d_in[5];
    const float* bn_var   = (const float*)d_in[6];
    const float* Wv       = (const float*)d_in[7];
    const float* bv       = (const float*)d_in[8];
    float* out = (float*)d_out;

    cudaFuncSetAttribute(flashm_kernel,
                         cudaFuncAttributeMaxDynamicSharedMemorySize, SMEM_TOTAL);

    proj_kernel<<<dim3(HW / 64, CK / 64, NB), 256>>>(
        x, Wk, bk, bn_gamma, bn_beta, bn_mean, bn_var, 1);
    proj_kernel<<<dim3(HW / 64, CV / 64, NB), 256>>>(
        x, Wv, bv, nullptr, nullptr, nullptr, nullptr, 0);
    flashm_kernel<<<dim3(HW / BQ, NB), 256, SMEM_TOTAL>>>(out);
}

// round 9
// speedup vs baseline: 6.7825x; 1.1371x over previous
#include <cuda_runtime.h>
#include <cuda_bf16.h>
#include <cstdint>
#include <math.h>

#define HW   4096
#define NB   4
#define CIN  256
#define CK   64
#define CV   256
#define BQ   128
#define BK   64
#define NKT  (HW / BK)

// Row pitch inside tiles: 144 B (72 bf16) -> conflict-free ldmatrix
#define PITCHE 72           // elements
#define KT_BYTES  (64 * 144)     // 9216
#define VT_BYTES  (256 * 144)    // 36864

// ---------------- pre-tiled bf16 hi/lo scratch ----------------
// K tiles: [b][kt][r(64)][72]   (token rows, d columns)
__device__ __align__(1024) __nv_bfloat16 g_kth[NB * 64 * 64 * PITCHE];
__device__ __align__(1024) __nv_bfloat16 g_ktl[NB * 64 * 64 * PITCHE];
// V tiles: [b][kt][c(256)][72]  (channel rows, j columns)
__device__ __align__(1024) __nv_bfloat16 g_vth[NB * 64 * 256 * PITCHE];
__device__ __align__(1024) __nv_bfloat16 g_vtl[NB * 64 * 256 * PITCHE];

// ---------------- helpers ----------------
__device__ __forceinline__ uint32_t smem_u32(const void* p) {
    uint32_t a;
    asm("{ .reg .u64 t; cvta.to.shared.u64 t, %1; cvt.u32.u64 %0, t; }" : "=r"(a) : "l"(p));
    return a;
}
__device__ __forceinline__ void bulkcp(uint32_t dst, const void* src, uint32_t bytes,
                                       uint32_t mbar) {
    asm volatile(
        "cp.async.bulk.shared::cluster.global.mbarrier::complete_tx::bytes [%0], [%1], %2, [%3];"
        :: "r"(dst), "l"(src), "r"(bytes), "r"(mbar) : "memory");
}
#define MBARRIER_INIT(mb, cnt) \
    asm volatile("mbarrier.init.shared.b64 [%0], %1;" :: "r"((uint32_t)(mb)), "r"((uint32_t)(cnt)) : "memory")
#define MBARRIER_EXPECT_TX(mb, tx) \
    asm volatile("mbarrier.arrive.expect_tx.shared.b64 _, [%0], %1;" :: "r"((uint32_t)(mb)), "r"((uint32_t)(tx)) : "memory")
#define MBARRIER_INVAL(mb) \
    asm volatile("mbarrier.inval.shared.b64 [%0];" :: "r"((uint32_t)(mb)) : "memory")
#define FENCE_ASYNC_SHARED() asm volatile("fence.proxy.async.shared::cta;" ::: "memory")
#define MBARRIER_WAIT_PARITY(mb, par) do { \
    uint32_t _mb = (uint32_t)(mb); uint32_t _p = (uint32_t)(par); uint32_t _done; \
    asm volatile("{\n\t.reg .pred p;\n\t" \
        "mbarrier.try_wait.parity.acquire.cta.shared::cta.b64 p, [%1], %2;\n\t" \
        "selp.b32 %0, 1, 0, p;\n\t}" : "=r"(_done) : "r"(_mb), "r"(_p) : "memory"); \
    if (!_done) { \
        asm volatile("{\n\t.reg .pred P1;\n\t" \
            "WL_%=:\n\t" \
            "mbarrier.try_wait.parity.acquire.cta.shared::cta.b64 P1, [%0], %1, 0x989680;\n\t" \
            "@P1 bra.uni WD_%=;\n\t" \
            "bra.uni WL_%=;\n\t" \
            "WD_%=:\n\t}" :: "r"(_mb), "r"(_p) : "memory"); \
    } } while (0)

__device__ __forceinline__ void ldsm4(uint32_t& r0, uint32_t& r1, uint32_t& r2, uint32_t& r3,
                                      uint32_t addr) {
    asm volatile("ldmatrix.sync.aligned.m8n8.x4.shared.b16 {%0,%1,%2,%3}, [%4];"
                 : "=r"(r0), "=r"(r1), "=r"(r2), "=r"(r3) : "r"(addr));
}
__device__ __forceinline__ void mma16816(float (&d)[4],
                                         uint32_t a0, uint32_t a1, uint32_t a2, uint32_t a3,
                                         uint32_t b0, uint32_t b1) {
    asm volatile("mma.sync.aligned.m16n8k16.row.col.f32.bf16.bf16.f32 "
                 "{%0,%1,%2,%3}, {%4,%5,%6,%7}, {%8,%9}, {%0,%1,%2,%3};"
                 : "+f"(d[0]), "+f"(d[1]), "+f"(d[2]), "+f"(d[3])
                 : "r"(a0), "r"(a1), "r"(a2), "r"(a3), "r"(b0), "r"(b1));
}

__device__ __forceinline__ void bsplit(float x, __nv_bfloat16& h, __nv_bfloat16& l) {
    h = __float2bfloat16(x);
    l = __float2bfloat16(x - __bfloat162float(h));
}
__device__ __forceinline__ uint32_t pack2(__nv_bfloat16 a, __nv_bfloat16 b) {
    __nv_bfloat162 t(a, b);
    return *reinterpret_cast<uint32_t*>(&t);
}
__device__ __forceinline__ uint32_t packhi(float x, float y) {
    return pack2(__float2bfloat16(x), __float2bfloat16(y));
}
__device__ __forceinline__ uint32_t packlo(float x, float y) {
    __nv_bfloat16 hx = __float2bfloat16(x), hy = __float2bfloat16(y);
    return pack2(__float2bfloat16(x - __bfloat162float(hx)),
                 __float2bfloat16(y - __bfloat162float(hy)));
}

// ---------------- smem layout (bytes); PITCH=144 rows -------------
#define PITCH  144
#define MBAR0  18432 * 2 + 147456          // after all tiles (see below)
#define QH_OFF 0
#define QL_OFF 18432
#define KBASE  36864
#define KH(st) (KBASE + (st) * KT_BYTES)
#define KL(st) (KBASE + 2 * KT_BYTES + (st) * KT_BYTES)
#define VBASE  (KBASE + 4 * KT_BYTES)
#define VH(st) (VBASE + (st) * VT_BYTES)
#define VL(st) (VBASE + 2 * VT_BYTES + (st) * VT_BYTES)
#define MB_OFF (VBASE + 4 * VT_BYTES)      // 221184
#define SMEM_TOTAL (MB_OFF + 64)           // 221248
#define OS_OFF 36864                        // epilogue O staging (reuses K/V region)
#define OPITCH 132

// ---------------------------------------------------------------------------
// Combined projection: blockIdx.y==0 -> K proj (BN fold), else V proj.
// Writes bf16 hi/lo directly into the pre-tiled pitched layouts.
// ---------------------------------------------------------------------------
__global__ __launch_bounds__(256) void proj_kernel(
    const float* __restrict__ x,
    const float* __restrict__ Wk, const float* __restrict__ bk,
    const float* __restrict__ bn_gamma, const float* __restrict__ bn_beta,
    const float* __restrict__ bn_mean,  const float* __restrict__ bn_var,
    const float* __restrict__ Wv, const float* __restrict__ bv)
{
    __shared__ float xs[64][64];
    __shared__ float ws[64][68];

    const int is_k = (blockIdx.y == 0);
    const float* W    = is_k ? Wk : Wv;
    const float* bias = is_k ? bk : bv;
    const int ko0 = is_k ? 0 : (blockIdx.y - 1) * 64;

    const int t0  = blockIdx.x * 64;
    const int kt  = blockIdx.x;          // key-tile index (t0 = kt*64)
    const int b   = blockIdx.z;
    const int tid = threadIdx.x;
    const int ti  = tid >> 4;
    const int tj  = tid & 15;

    float acc[4][4] = {};

    for (int c0 = 0; c0 < CIN; c0 += 64) {
        #pragma unroll
        for (int it = 0; it < 4; it++) {
            int v = tid + it * 256;
            int c = v >> 4, i4 = (v & 15) << 2;
            *(float4*)&xs[c][i4] =
                *(const float4*)&x[((size_t)(b * CIN + c0 + c)) * HW + t0 + i4];
        }
        #pragma unroll
        for (int it = 0; it < 4; it++) {
            int v = tid + it * 256;
            int ko = v >> 4, c4 = (v & 15) << 2;
            float4 w = *(const float4*)&W[(ko0 + ko) * CIN + c0 + c4];
            ws[c4 + 0][ko] = w.x; ws[c4 + 1][ko] = w.y;
            ws[c4 + 2][ko] = w.z; ws[c4 + 3][ko] = w.w;
        }
        __syncthreads();

        #pragma unroll 8
        for (int c = 0; c < 64; c++) {
            float4 wv = *(float4*)&ws[c][ti * 4];
            float4 xv = *(float4*)&xs[c][tj * 4];
            float wr[4] = {wv.x, wv.y, wv.z, wv.w};
            float xr[4] = {xv.x, xv.y, xv.z, xv.w};
            #pragma unroll
            for (int ii = 0; ii < 4; ii++)
                #pragma unroll
                for (int jj = 0; jj < 4; jj++)
                    acc[ii][jj] = fmaf(wr[ii], xr[jj], acc[ii][jj]);
        }
        __syncthreads();
    }

    if (is_k) {
        // BN fold; write K tile rows r = tj*4+jj, cols d = ti*4..+3
        float kv[4][4];
        #pragma unroll
        for (int ii = 0; ii < 4; ii++) {
            int ko = ti * 4 + ii;
            float inv = bn_gamma[ko] * rsqrtf(bn_var[ko] + 1e-5f);
            float add = bn_beta[ko] - bn_mean[ko] * inv;
            float bz  = bias[ko];
            #pragma unroll
            for (int jj = 0; jj < 4; jj++)
                kv[jj][ii] = (acc[ii][jj] + bz) * inv + add;
        }
        #pragma unroll
        for (int jj = 0; jj < 4; jj++) {
            int r = tj * 4 + jj;
            __nv_bfloat16 h[4], l[4];
            #pragma unroll
            for (int ii = 0; ii < 4; ii++) bsplit(kv[jj][ii], h[ii], l[ii]);
            size_t base = ((size_t)((b * 64 + kt) * 64 + r)) * PITCHE + ti * 4;
            *(uint32_t*)&g_kth[base]     = pack2(h[0], h[1]);
            *(uint32_t*)&g_kth[base + 2] = pack2(h[2], h[3]);
            *(uint32_t*)&g_ktl[base]     = pack2(l[0], l[1]);
            *(uint32_t*)&g_ktl[base + 2] = pack2(l[2], l[3]);
        }
    } else {
        // V tile rows c = ko0+ti*4+ii, cols j = tj*4..+3
        #pragma unroll
        for (int ii = 0; ii < 4; ii++) {
            int c = ko0 + ti * 4 + ii;
            float bz = bias[c];
            __nv_bfloat16 h[4], l[4];
            #pragma unroll
            for (int jj = 0; jj < 4; jj++) bsplit(acc[ii][jj] + bz, h[jj], l[jj]);
            size_t base = ((size_t)((b * 64 + kt) * 256 + c)) * PITCHE + tj * 4;
            *(uint32_t*)&g_vth[base]     = pack2(h[0], h[1]);
            *(uint32_t*)&g_vth[base + 2] = pack2(h[2], h[3]);
            *(uint32_t*)&g_vtl[base]     = pack2(l[0], l[1]);
            *(uint32_t*)&g_vtl[base + 2] = pack2(l[2], l[3]);
        }
    }
}

// ---------------------------------------------------------------------------
// HMMA flash attention with bulk-copy tile pipeline.
// ---------------------------------------------------------------------------
__global__ __launch_bounds__(256, 1) void flashm_kernel(float* __restrict__ out)
{
    extern __shared__ char smem[];
    const uint32_t sb = smem_u32(smem);
    const int tid  = threadIdx.x;
    const int w    = tid >> 5;
    const int lane = tid & 31;
    const int g    = lane >> 2;
    const int tig  = lane & 3;
    const int i0   = w * 16;

    const int qb = blockIdx.x;           // query block (128 rows = key tiles 2qb, 2qb+1)
    const int q0 = qb * BQ;
    const int b  = blockIdx.y;

    const char* kth = (const char*)g_kth + (size_t)(b * 64) * KT_BYTES;
    const char* ktl = (const char*)g_ktl + (size_t)(b * 64) * KT_BYTES;
    const char* vth = (const char*)g_vth + (size_t)(b * 64) * VT_BYTES;
    const char* vtl = (const char*)g_vtl + (size_t)(b * 64) * VT_BYTES;

    const uint32_t mb0 = sb + MB_OFF;
    const uint32_t mb1 = sb + MB_OFF + 8;

    if (tid == 0) {
        MBARRIER_INIT(mb0, 1);
        MBARRIER_INIT(mb1, 1);
        FENCE_ASYNC_SHARED();
    }
    __syncthreads();

    if (tid == 0) {
        // phase 0 of mb0 covers: Q (2x18432) + stage-0 K/V (92160)
        MBARRIER_EXPECT_TX(mb0, 36864 + 92160);
        bulkcp(sb + QH_OFF, kth + (size_t)(2 * qb) * KT_BYTES, 2 * KT_BYTES, mb0);
        bulkcp(sb + QL_OFF, ktl + (size_t)(2 * qb) * KT_BYTES, 2 * KT_BYTES, mb0);
        bulkcp(sb + KH(0), kth, KT_BYTES, mb0);
        bulkcp(sb + KL(0), ktl, KT_BYTES, mb0);
        bulkcp(sb + VH(0), vth, VT_BYTES, mb0);
        bulkcp(sb + VL(0), vtl, VT_BYTES, mb0);
    }

    float m0 = -1e30f, m1 = -1e30f, l0 = 0.0f, l1 = 0.0f;
    float O[32][4];
    #pragma unroll
    for (int t = 0; t < 32; t++)
        #pragma unroll
        for (int r = 0; r < 4; r++) O[t][r] = 0.0f;

    const uint32_t a_row = (uint32_t)(lane & 15);
    const uint32_t a_col = (uint32_t)((lane & 16) >> 1);
    const uint32_t b_row = (uint32_t)((lane & 7) + ((lane & 16) >> 1));
    const uint32_t b_col = (uint32_t)(lane & 8);

    int ph0 = 0, ph1 = 0;

    for (int kt = 0; kt < NKT; kt++) {
        const int st = kt & 1;
        if (st == 0) { MBARRIER_WAIT_PARITY(mb0, ph0); ph0 ^= 1; }
        else         { MBARRIER_WAIT_PARITY(mb1, ph1); ph1 ^= 1; }
        __syncthreads();   // all warps done with buffers of stage st^1 (iter kt-1)

        if (kt + 1 < NKT && tid == 0) {
            const uint32_t mbn = (st == 0) ? mb1 : mb0;
            const int nst = st ^ 1;
            MBARRIER_EXPECT_TX(mbn, 92160);
            bulkcp(sb + KH(nst), kth + (size_t)(kt + 1) * KT_BYTES, KT_BYTES, mbn);
            bulkcp(sb + KL(nst), ktl + (size_t)(kt + 1) * KT_BYTES, KT_BYTES, mbn);
            bulkcp(sb + VH(nst), vth + (size_t)(kt + 1) * VT_BYTES, VT_BYTES, mbn);
            bulkcp(sb + VL(nst), vtl + (size_t)(kt + 1) * VT_BYTES, VT_BYTES, mbn);
        }

        // ---------------- S = Q K^T (16 x 64), 3-way split ----------------
        float S[8][4];
        #pragma unroll
        for (int t = 0; t < 8; t++)
            #pragma unroll
            for (int r = 0; r < 4; r++) S[t][r] = 0.0f;

        #pragma unroll
        for (int kk = 0; kk < 4; kk++) {
            uint32_t qoff = (i0 + a_row) * PITCH + (kk * 16 + a_col) * 2;
            uint32_t aH0, aH1, aH2, aH3, aL0, aL1, aL2, aL3;
            ldsm4(aH0, aH1, aH2, aH3, sb + QH_OFF + qoff);
            ldsm4(aL0, aL1, aL2, aL3, sb + QL_OFF + qoff);
            #pragma unroll
            for (int p = 0; p < 4; p++) {
                uint32_t koff = (p * 16 + b_row) * PITCH + (kk * 16 + b_col) * 2;
                uint32_t bH0, bH1, bH2, bH3, bL0, bL1, bL2, bL3;
                ldsm4(bH0, bH1, bH2, bH3, sb + KH(st) + koff);
                ldsm4(bL0, bL1, bL2, bL3, sb + KL(st) + koff);
                mma16816(S[2*p],   aH0, aH1, aH2, aH3, bH0, bH1);
                mma16816(S[2*p],   aH0, aH1, aH2, aH3, bL0, bL1);
                mma16816(S[2*p],   aL0, aL1, aL2, aL3, bH0, bH1);
                mma16816(S[2*p+1], aH0, aH1, aH2, aH3, bH2, bH3);
                mma16816(S[2*p+1], aH0, aH1, aH2, aH3, bL2, bL3);
                mma16816(S[2*p+1], aL0, aL1, aL2, aL3, bH2, bH3);
            }
        }

        // ---------------- online softmax ----------------
        float mx0 = -1e30f, mx1 = -1e30f;
        #pragma unroll
        for (int t = 0; t < 8; t++) {
            mx0 = fmaxf(mx0, fmaxf(S[t][0], S[t][1]));
            mx1 = fmaxf(mx1, fmaxf(S[t][2], S[t][3]));
        }
        mx0 = fmaxf(mx0, __shfl_xor_sync(0xffffffffu, mx0, 1));
        mx0 = fmaxf(mx0, __shfl_xor_sync(0xffffffffu, mx0, 2));
        mx1 = fmaxf(mx1, __shfl_xor_sync(0xffffffffu, mx1, 1));
        mx1 = fmaxf(mx1, __shfl_xor_sync(0xffffffffu, mx1, 2));
        mx0 = fmaxf(mx0, m0);
        mx1 = fmaxf(mx1, m1);
        const float sc0 = __expf(m0 - mx0);
        const float sc1 = __expf(m1 - mx1);
        m0 = mx0; m1 = mx1;

        float r0 = 0.0f, r1 = 0.0f;
        #pragma unroll
        for (int t = 0; t < 8; t++) {
            S[t][0] = __expf(S[t][0] - mx0);
            S[t][1] = __expf(S[t][1] - mx0);
            S[t][2] = __expf(S[t][2] - mx1);
            S[t][3] = __expf(S[t][3] - mx1);
            r0 += S[t][0] + S[t][1];
            r1 += S[t][2] + S[t][3];
        }
        r0 += __shfl_xor_sync(0xffffffffu, r0, 1);
        r0 += __shfl_xor_sync(0xffffffffu, r0, 2);
        r1 += __shfl_xor_sync(0xffffffffu, r1, 1);
        r1 += __shfl_xor_sync(0xffffffffu, r1, 2);
        l0 = l0 * sc0 + r0;
        l1 = l1 * sc1 + r1;

        #pragma unroll
        for (int t = 0; t < 32; t++) {
            O[t][0] *= sc0; O[t][1] *= sc0;
            O[t][2] *= sc1; O[t][3] *= sc1;
        }

        // ---------------- P repack ----------------
        uint32_t Ph[4][4], Pl[4][4];
        #pragma unroll
        for (int kk = 0; kk < 4; kk++) {
            Ph[kk][0] = packhi(S[2*kk][0],   S[2*kk][1]);
            Ph[kk][1] = packhi(S[2*kk][2],   S[2*kk][3]);
            Ph[kk][2] = packhi(S[2*kk+1][0], S[2*kk+1][1]);
            Ph[kk][3] = packhi(S[2*kk+1][2], S[2*kk+1][3]);
            Pl[kk][0] = packlo(S[2*kk][0],   S[2*kk][1]);
            Pl[kk][1] = packlo(S[2*kk][2],   S[2*kk][3]);
            Pl[kk][2] = packlo(S[2*kk+1][0], S[2*kk+1][1]);
            Pl[kk][3] = packlo(S[2*kk+1][2], S[2*kk+1][3]);
        }

        // ---------------- O += P V  (16 x 256), 3-way split ----------------
        #pragma unroll
        for (int kk = 0; kk < 4; kk++) {
            #pragma unroll
            for (int p = 0; p < 16; p++) {
                uint32_t voff = (p * 16 + b_row) * PITCH + (kk * 16 + b_col) * 2;
                uint32_t vH0, vH1, vH2, vH3, vL0, vL1, vL2, vL3;
                ldsm4(vH0, vH1, vH2, vH3, sb + VH(st) + voff);
                ldsm4(vL0, vL1, vL2, vL3, sb + VL(st) + voff);
                mma16816(O[2*p],   Ph[kk][0], Ph[kk][1], Ph[kk][2], Ph[kk][3], vH0, vH1);
                mma16816(O[2*p],   Pl[kk][0], Pl[kk][1], Pl[kk][2], Pl[kk][3], vH0, vH1);
                mma16816(O[2*p],   Ph[kk][0], Ph[kk][1], Ph[kk][2], Ph[kk][3], vL0, vL1);
                mma16816(O[2*p+1], Ph[kk][0], Ph[kk][1], Ph[kk][2], Ph[kk][3], vH2, vH3);
                mma16816(O[2*p+1], Pl[kk][0], Pl[kk][1], Pl[kk][2], Pl[kk][3], vH2, vH3);
                mma16816(O[2*p+1], Ph[kk][0], Ph[kk][1], Ph[kk][2], Ph[kk][3], vL2, vL3);
            }
        }
    }

    // ---------------- epilogue: stage O in smem, coalesced store ----------------
    __syncthreads();
    {
        float* os = (float*)(smem + OS_OFF);
        const float il0 = 1.0f / l0;
        const float il1 = 1.0f / l1;
        #pragma unroll
        for (int t = 0; t < 32; t++) {
            int c = t * 8 + tig * 2;
            os[(c    ) * OPITCH + i0 + g    ] = O[t][0] * il0;
            os[(c + 1) * OPITCH + i0 + g    ] = O[t][1] * il0;
            os[(c    ) * OPITCH + i0 + g + 8] = O[t][2] * il1;
            os[(c + 1) * OPITCH + i0 + g + 8] = O[t][3] * il1;
        }
        __syncthreads();
        #pragma unroll
        for (int cc = 0; cc < 32; cc++) {
            int c = w * 32 + cc;
            float4 v = *(float4*)&os[c * OPITCH + lane * 4];
            *(float4*)&out[((size_t)(b * CV + c)) * HW + q0 + lane * 4] = v;
        }
    }
    __syncthreads();
    if (tid == 0) { MBARRIER_INVAL(mb0); MBARRIER_INVAL(mb1); }
}

// ---------------------------------------------------------------------------
extern "C" void kernel_launch(void* const* d_in, const int* in_sizes, int n_in,
                              void* d_out, int out_size)
{
    const float* x        = (const float*)d_in[0];
    const float* Wk       = (const float*)d_in[1];
    const float* bk       = (const float*)d_in[2];
    const float* bn_gamma = (const float*)d_in[3];
    const float* bn_beta  = (const float*)d_in[4];
    const float* bn_mean  = (const float*)d_in[5];
    const float* bn_var   = (const float*)d_in[6];
    const float* Wv       = (const float*)d_in[7];
    const float* bv       = (const float*)d_in[8];
    float* out = (float*)d_out;

    cudaFuncSetAttribute(flashm_kernel,
                         cudaFuncAttributeMaxDynamicSharedMemorySize, SMEM_TOTAL);

    // y = 0: K proj (BN fold).  y = 1..4: V proj 64-channel slabs.
    proj_kernel<<<dim3(HW / 64, 5, NB), 256>>>(
        x, Wk, bk, bn_gamma, bn_beta, bn_mean, bn_var, Wv, bv);
    flashm_kernel<<<dim3(HW / BQ, NB), 256, SMEM_TOTAL>>>(out);
}

// round 11
// speedup vs baseline: 10.7301x; 1.5820x over previous
#include <cuda_runtime.h>
#include <cuda_fp16.h>
#include <cstdint>
#include <math.h>

#define HW   4096
#define NB   4
#define CIN  256
#define CK   64
#define CV   256
#define BQ   128
#define BK   64
#define NKT  (HW / BK)

// Row pitch inside tiles: 144 B (72 fp16) -> conflict-free ldmatrix
#define PITCHE 72                 // elements
#define KT_BYTES  (64 * 144)      // 9216
#define VT_BYTES  (256 * 144)     // 36864

// ---------------- pre-tiled fp16 scratch ----------------
// K tiles: [b][kt][r(64)][72] hi/lo (token rows, d columns)
__device__ __align__(1024) __half g_kth[NB * 64 * 64 * PITCHE];
__device__ __align__(1024) __half g_ktl[NB * 64 * 64 * PITCHE];
// V tiles: [b][kt][c(256)][72] single fp16 (channel rows, j columns)
__device__ __align__(1024) __half g_vth[NB * 64 * 256 * PITCHE];

// ---------------- helpers ----------------
__device__ __forceinline__ uint32_t smem_u32(const void* p) {
    uint32_t a;
    asm("{ .reg .u64 t; cvta.to.shared.u64 t, %1; cvt.u32.u64 %0, t; }" : "=r"(a) : "l"(p));
    return a;
}
__device__ __forceinline__ void bulkcp(uint32_t dst, const void* src, uint32_t bytes,
                                       uint32_t mbar) {
    asm volatile(
        "cp.async.bulk.shared::cluster.global.mbarrier::complete_tx::bytes [%0], [%1], %2, [%3];"
        :: "r"(dst), "l"(src), "r"(bytes), "r"(mbar) : "memory");
}
#define MBARRIER_INIT(mb, cnt) \
    asm volatile("mbarrier.init.shared.b64 [%0], %1;" :: "r"((uint32_t)(mb)), "r"((uint32_t)(cnt)) : "memory")
#define MBARRIER_EXPECT_TX(mb, tx) \
    asm volatile("mbarrier.arrive.expect_tx.shared.b64 _, [%0], %1;" :: "r"((uint32_t)(mb)), "r"((uint32_t)(tx)) : "memory")
#define MBARRIER_INVAL(mb) \
    asm volatile("mbarrier.inval.shared.b64 [%0];" :: "r"((uint32_t)(mb)) : "memory")
#define FENCE_ASYNC_SHARED() asm volatile("fence.proxy.async.shared::cta;" ::: "memory")
#define MBARRIER_WAIT_PARITY(mb, par) do { \
    uint32_t _mb = (uint32_t)(mb); uint32_t _p = (uint32_t)(par); uint32_t _done; \
    asm volatile("{\n\t.reg .pred p;\n\t" \
        "mbarrier.try_wait.parity.acquire.cta.shared::cta.b64 p, [%1], %2;\n\t" \
        "selp.b32 %0, 1, 0, p;\n\t}" : "=r"(_done) : "r"(_mb), "r"(_p) : "memory"); \
    if (!_done) { \
        asm volatile("{\n\t.reg .pred P1;\n\t" \
            "WL_%=:\n\t" \
            "mbarrier.try_wait.parity.acquire.cta.shared::cta.b64 P1, [%0], %1, 0x989680;\n\t" \
            "@P1 bra.uni WD_%=;\n\t" \
            "bra.uni WL_%=;\n\t" \
            "WD_%=:\n\t}" :: "r"(_mb), "r"(_p) : "memory"); \
    } } while (0)

__device__ __forceinline__ void ldsm4(uint32_t& r0, uint32_t& r1, uint32_t& r2, uint32_t& r3,
                                      uint32_t addr) {
    asm volatile("ldmatrix.sync.aligned.m8n8.x4.shared.b16 {%0,%1,%2,%3}, [%4];"
                 : "=r"(r0), "=r"(r1), "=r"(r2), "=r"(r3) : "r"(addr));
}
__device__ __forceinline__ void mma16816(float (&d)[4],
                                         uint32_t a0, uint32_t a1, uint32_t a2, uint32_t a3,
                                         uint32_t b0, uint32_t b1) {
    asm volatile("mma.sync.aligned.m16n8k16.row.col.f32.f16.f16.f32 "
                 "{%0,%1,%2,%3}, {%4,%5,%6,%7}, {%8,%9}, {%0,%1,%2,%3};"
                 : "+f"(d[0]), "+f"(d[1]), "+f"(d[2]), "+f"(d[3])
                 : "r"(a0), "r"(a1), "r"(a2), "r"(a3), "r"(b0), "r"(b1));
}

__device__ __forceinline__ void hsplit(float x, __half& h, __half& l) {
    h = __float2half_rn(x);
    l = __float2half_rn(x - __half2float(h));
}
__device__ __forceinline__ uint32_t pack2h(__half a, __half b) {
    __half2 t(a, b);
    return *reinterpret_cast<uint32_t*>(&t);
}
__device__ __forceinline__ uint32_t packh2(float x, float y) {
    __half2 t = __floats2half2_rn(x, y);
    return *reinterpret_cast<uint32_t*>(&t);
}

// ---------------- smem layout (bytes); PITCH=144 rows -------------
#define PITCH  144
#define QH_OFF 0
#define QL_OFF 18432
#define KBASE  36864
#define KH(st) (KBASE + (st) * KT_BYTES)
#define KL(st) (KBASE + 2 * KT_BYTES + (st) * KT_BYTES)
#define VBASE  (KBASE + 4 * KT_BYTES)           // 73728
#define VS(st) (VBASE + (st) * VT_BYTES)
#define MB_OFF (VBASE + 2 * VT_BYTES)           // 147456
#define SMEM_TOTAL (MB_OFF + 64)                // 147520
#define OS_OFF 0                                // epilogue O staging (tiles dead)
#define OPITCH 132
#define STAGE_TX (2 * KT_BYTES + VT_BYTES)      // 55296

// ---------------------------------------------------------------------------
// Combined projection: blockIdx.y==0 -> K proj (BN fold, fp16 hi/lo tiles),
// else V proj (single fp16 tiles).
// ---------------------------------------------------------------------------
__global__ __launch_bounds__(256) void proj_kernel(
    const float* __restrict__ x,
    const float* __restrict__ Wk, const float* __restrict__ bk,
    const float* __restrict__ bn_gamma, const float* __restrict__ bn_beta,
    const float* __restrict__ bn_mean,  const float* __restrict__ bn_var,
    const float* __restrict__ Wv, const float* __restrict__ bv)
{
    __shared__ float xs[64][64];
    __shared__ float ws[64][68];

    const int is_k = (blockIdx.y == 0);
    const float* W    = is_k ? Wk : Wv;
    const float* bias = is_k ? bk : bv;
    const int ko0 = is_k ? 0 : (blockIdx.y - 1) * 64;

    const int t0  = blockIdx.x * 64;
    const int kt  = blockIdx.x;
    const int b   = blockIdx.z;
    const int tid = threadIdx.x;
    const int ti  = tid >> 4;
    const int tj  = tid & 15;

    float acc[4][4] = {};

    for (int c0 = 0; c0 < CIN; c0 += 64) {
        #pragma unroll
        for (int it = 0; it < 4; it++) {
            int v = tid + it * 256;
            int c = v >> 4, i4 = (v & 15) << 2;
            *(float4*)&xs[c][i4] =
                *(const float4*)&x[((size_t)(b * CIN + c0 + c)) * HW + t0 + i4];
        }
        #pragma unroll
        for (int it = 0; it < 4; it++) {
            int v = tid + it * 256;
            int ko = v >> 4, c4 = (v & 15) << 2;
            float4 w = *(const float4*)&W[(ko0 + ko) * CIN + c0 + c4];
            ws[c4 + 0][ko] = w.x; ws[c4 + 1][ko] = w.y;
            ws[c4 + 2][ko] = w.z; ws[c4 + 3][ko] = w.w;
        }
        __syncthreads();

        #pragma unroll 8
        for (int c = 0; c < 64; c++) {
            float4 wv = *(float4*)&ws[c][ti * 4];
            float4 xv = *(float4*)&xs[c][tj * 4];
            float wr[4] = {wv.x, wv.y, wv.z, wv.w};
            float xr[4] = {xv.x, xv.y, xv.z, xv.w};
            #pragma unroll
            for (int ii = 0; ii < 4; ii++)
                #pragma unroll
                for (int jj = 0; jj < 4; jj++)
                    acc[ii][jj] = fmaf(wr[ii], xr[jj], acc[ii][jj]);
        }
        __syncthreads();
    }

    if (is_k) {
        float kv[4][4];
        #pragma unroll
        for (int ii = 0; ii < 4; ii++) {
            int ko = ti * 4 + ii;
            float inv = bn_gamma[ko] * rsqrtf(bn_var[ko] + 1e-5f);
            float add = bn_beta[ko] - bn_mean[ko] * inv;
            float bz  = bias[ko];
            #pragma unroll
            for (int jj = 0; jj < 4; jj++)
                kv[jj][ii] = (acc[ii][jj] + bz) * inv + add;
        }
        #pragma unroll
        for (int jj = 0; jj < 4; jj++) {
            int r = tj * 4 + jj;
            __half h[4], l[4];
            #pragma unroll
            for (int ii = 0; ii < 4; ii++) hsplit(kv[jj][ii], h[ii], l[ii]);
            size_t base = ((size_t)((b * 64 + kt) * 64 + r)) * PITCHE + ti * 4;
            *(uint32_t*)&g_kth[base]     = pack2h(h[0], h[1]);
            *(uint32_t*)&g_kth[base + 2] = pack2h(h[2], h[3]);
            *(uint32_t*)&g_ktl[base]     = pack2h(l[0], l[1]);
            *(uint32_t*)&g_ktl[base + 2] = pack2h(l[2], l[3]);
        }
    } else {
        #pragma unroll
        for (int ii = 0; ii < 4; ii++) {
            int c = ko0 + ti * 4 + ii;
            float bz = bias[c];
            size_t base = ((size_t)((b * 64 + kt) * 256 + c)) * PITCHE + tj * 4;
            *(uint32_t*)&g_vth[base]     = packh2(acc[ii][0] + bz, acc[ii][1] + bz);
            *(uint32_t*)&g_vth[base + 2] = packh2(acc[ii][2] + bz, acc[ii][3] + bz);
        }
    }
}

// ---------------------------------------------------------------------------
// HMMA fp16 flash attention: S 3-term split, PV single fp16.
// Named-barrier producer sync (no per-iter __syncthreads) lets warps skew.
// ---------------------------------------------------------------------------
__global__ __launch_bounds__(256, 1) void flashm_kernel(float* __restrict__ out)
{
    extern __shared__ char smem[];
    const uint32_t sb = smem_u32(smem);
    const int tid  = threadIdx.x;
    const int w    = tid >> 5;
    const int lane = tid & 31;
    const int g    = lane >> 2;
    const int tig  = lane & 3;
    const int i0   = w * 16;

    const int qb = blockIdx.x;
    const int q0 = qb * BQ;
    const int b  = blockIdx.y;

    const char* kth = (const char*)g_kth + (size_t)(b * 64) * KT_BYTES;
    const char* ktl = (const char*)g_ktl + (size_t)(b * 64) * KT_BYTES;
    const char* vth = (const char*)g_vth + (size_t)(b * 64) * VT_BYTES;

    const uint32_t mb0 = sb + MB_OFF;
    const uint32_t mb1 = sb + MB_OFF + 8;

    if (tid == 0) {
        MBARRIER_INIT(mb0, 1);
        MBARRIER_INIT(mb1, 1);
        FENCE_ASYNC_SHARED();
    }
    __syncthreads();

    if (tid == 0) {
        // mb0 phase 0: Q hi/lo (2x18432) + stage-0 K/V (55296)
        MBARRIER_EXPECT_TX(mb0, 36864 + STAGE_TX);
        bulkcp(sb + QH_OFF, kth + (size_t)(2 * qb) * KT_BYTES, 2 * KT_BYTES, mb0);
        bulkcp(sb + QL_OFF, ktl + (size_t)(2 * qb) * KT_BYTES, 2 * KT_BYTES, mb0);
        bulkcp(sb + KH(0), kth, KT_BYTES, mb0);
        bulkcp(sb + KL(0), ktl, KT_BYTES, mb0);
        bulkcp(sb + VS(0), vth, VT_BYTES, mb0);
        // mb1 phase 0: stage-1 K/V
        MBARRIER_EXPECT_TX(mb1, STAGE_TX);
        bulkcp(sb + KH(1), kth + (size_t)KT_BYTES, KT_BYTES, mb1);
        bulkcp(sb + KL(1), ktl + (size_t)KT_BYTES, KT_BYTES, mb1);
        bulkcp(sb + VS(1), vth + (size_t)VT_BYTES, VT_BYTES, mb1);
    }

    float m0 = -1e30f, m1 = -1e30f, l0 = 0.0f, l1 = 0.0f;
    float O[32][4];
    #pragma unroll
    for (int t = 0; t < 32; t++)
        #pragma unroll
        for (int r = 0; r < 4; r++) O[t][r] = 0.0f;

    const uint32_t a_row = (uint32_t)(lane & 15);
    const uint32_t a_col = (uint32_t)((lane & 16) >> 1);
    const uint32_t b_row = (uint32_t)((lane & 7) + ((lane & 16) >> 1));
    const uint32_t b_col = (uint32_t)(lane & 8);

    int ph0 = 0, ph1 = 0;

    for (int kt = 0; kt < NKT; kt++) {
        const int st = kt & 1;
        const uint32_t mb = st ? mb1 : mb0;
        if (st == 0) { MBARRIER_WAIT_PARITY(mb0, ph0); ph0 ^= 1; }
        else         { MBARRIER_WAIT_PARITY(mb1, ph1); ph1 ^= 1; }

        // ---------------- S = Q K^T (16 x 64), fp16 3-term split ----------------
        float S[8][4];
        #pragma unroll
        for (int t = 0; t < 8; t++)
            #pragma unroll
            for (int r = 0; r < 4; r++) S[t][r] = 0.0f;

        #pragma unroll
        for (int kk = 0; kk < 4; kk++) {
            uint32_t qoff = (i0 + a_row) * PITCH + (kk * 16 + a_col) * 2;
            uint32_t aH0, aH1, aH2, aH3, aL0, aL1, aL2, aL3;
            ldsm4(aH0, aH1, aH2, aH3, sb + QH_OFF + qoff);
            ldsm4(aL0, aL1, aL2, aL3, sb + QL_OFF + qoff);
            #pragma unroll
            for (int p = 0; p < 4; p++) {
                uint32_t koff = (p * 16 + b_row) * PITCH + (kk * 16 + b_col) * 2;
                uint32_t bH0, bH1, bH2, bH3, bL0, bL1, bL2, bL3;
                ldsm4(bH0, bH1, bH2, bH3, sb + KH(st) + koff);
                ldsm4(bL0, bL1, bL2, bL3, sb + KL(st) + koff);
                mma16816(S[2*p],   aH0, aH1, aH2, aH3, bH0, bH1);
                mma16816(S[2*p],   aH0, aH1, aH2, aH3, bL0, bL1);
                mma16816(S[2*p],   aL0, aL1, aL2, aL3, bH0, bH1);
                mma16816(S[2*p+1], aH0, aH1, aH2, aH3, bH2, bH3);
                mma16816(S[2*p+1], aH0, aH1, aH2, aH3, bL2, bL3);
                mma16816(S[2*p+1], aL0, aL1, aL2, aL3, bH2, bH3);
            }
        }

        // ---------------- online softmax ----------------
        float mx0 = -1e30f, mx1 = -1e30f;
        #pragma unroll
        for (int t = 0; t < 8; t++) {
            mx0 = fmaxf(mx0, fmaxf(S[t][0], S[t][1]));
            mx1 = fmaxf(mx1, fmaxf(S[t][2], S[t][3]));
        }
        mx0 = fmaxf(mx0, __shfl_xor_sync(0xffffffffu, mx0, 1));
        mx0 = fmaxf(mx0, __shfl_xor_sync(0xffffffffu, mx0, 2));
        mx1 = fmaxf(mx1, __shfl_xor_sync(0xffffffffu, mx1, 1));
        mx1 = fmaxf(mx1, __shfl_xor_sync(0xffffffffu, mx1, 2));
        mx0 = fmaxf(mx0, m0);
        mx1 = fmaxf(mx1, m1);
        const float sc0 = __expf(m0 - mx0);
        const float sc1 = __expf(m1 - mx1);
        m0 = mx0; m1 = mx1;

        float r0 = 0.0f, r1 = 0.0f;
        #pragma unroll
        for (int t = 0; t < 8; t++) {
            S[t][0] = __expf(S[t][0] - mx0);
            S[t][1] = __expf(S[t][1] - mx0);
            S[t][2] = __expf(S[t][2] - mx1);
            S[t][3] = __expf(S[t][3] - mx1);
            r0 += S[t][0] + S[t][1];
            r1 += S[t][2] + S[t][3];
        }
        r0 += __shfl_xor_sync(0xffffffffu, r0, 1);
        r0 += __shfl_xor_sync(0xffffffffu, r0, 2);
        r1 += __shfl_xor_sync(0xffffffffu, r1, 1);
        r1 += __shfl_xor_sync(0xffffffffu, r1, 2);
        l0 = l0 * sc0 + r0;
        l1 = l1 * sc1 + r1;

        #pragma unroll
        for (int t = 0; t < 32; t++) {
            O[t][0] *= sc0; O[t][1] *= sc0;
            O[t][2] *= sc1; O[t][3] *= sc1;
        }

        // ---------------- P repack (fp16 single) ----------------
        uint32_t Ph[4][4];
        #pragma unroll
        for (int kk = 0; kk < 4; kk++) {
            Ph[kk][0] = packh2(S[2*kk][0],   S[2*kk][1]);
            Ph[kk][1] = packh2(S[2*kk][2],   S[2*kk][3]);
            Ph[kk][2] = packh2(S[2*kk+1][0], S[2*kk+1][1]);
            Ph[kk][3] = packh2(S[2*kk+1][2], S[2*kk+1][3]);
        }

        // ---------------- O += P V  (16 x 256), single fp16 ----------------
        #pragma unroll
        for (int kk = 0; kk < 4; kk++) {
            #pragma unroll
            for (int p = 0; p < 16; p++) {
                uint32_t voff = (p * 16 + b_row) * PITCH + (kk * 16 + b_col) * 2;
                uint32_t v0, v1, v2, v3;
                ldsm4(v0, v1, v2, v3, sb + VS(st) + voff);
                mma16816(O[2*p],   Ph[kk][0], Ph[kk][1], Ph[kk][2], Ph[kk][3], v0, v1);
                mma16816(O[2*p+1], Ph[kk][0], Ph[kk][1], Ph[kk][2], Ph[kk][3], v2, v3);
            }
        }

        // ---------------- stage-free handoff (named barriers 2+st) ----------------
        if (w == 0) {
            asm volatile("bar.sync %0, %1;" :: "r"(2 + st), "r"(256) : "memory");
            if (lane == 0 && kt + 2 < NKT) {
                MBARRIER_EXPECT_TX(mb, STAGE_TX);
                bulkcp(sb + KH(st), kth + (size_t)(kt + 2) * KT_BYTES, KT_BYTES, mb);
                bulkcp(sb + KL(st), ktl + (size_t)(kt + 2) * KT_BYTES, KT_BYTES, mb);
                bulkcp(sb + VS(st), vth + (size_t)(kt + 2) * VT_BYTES, VT_BYTES, mb);
            }
        } else {
            asm volatile("bar.arrive %0, %1;" :: "r"(2 + st), "r"(256) : "memory");
        }
    }

    // ---------------- epilogue: stage O in smem, coalesced store ----------------
    __syncthreads();
    {
        float* os = (float*)(smem + OS_OFF);
        const float il0 = 1.0f / l0;
        const float il1 = 1.0f / l1;
        #pragma unroll
        for (int t = 0; t < 32; t++) {
            int c = t * 8 + tig * 2;
            os[(c    ) * OPITCH + i0 + g    ] = O[t][0] * il0;
            os[(c + 1) * OPITCH + i0 + g    ] = O[t][1] * il0;
            os[(c    ) * OPITCH + i0 + g + 8] = O[t][2] * il1;
            os[(c + 1) * OPITCH + i0 + g + 8] = O[t][3] * il1;
        }
        __syncthreads();
        #pragma unroll
        for (int cc = 0; cc < 32; cc++) {
            int c = w * 32 + cc;
            float4 v = *(float4*)&os[c * OPITCH + lane * 4];
            *(float4*)&out[((size_t)(b * CV + c)) * HW + q0 + lane * 4] = v;
        }
    }
    __syncthreads();
    if (tid == 0) { MBARRIER_INVAL(mb0); MBARRIER_INVAL(mb1); }
}

// ---------------------------------------------------------------------------
extern "C" void kernel_launch(void* const* d_in, const int* in_sizes, int n_in,
                              void* d_out, int out_size)
{
    const float* x        = (const float*)d_in[0];
    const float* Wk       = (const float*)d_in[1];
    const float* bk       = (const float*)d_in[2];
    const float* bn_gamma = (const float*)d_in[3];
    const float* bn_beta  = (const float*)d_in[4];
    const float* bn_mean  = (const float*)d_in[5];
    const float* bn_var   = (const float*)d_in[6];
    const float* Wv       = (const float*)d_in[7];
    const float* bv       = (const float*)d_in[8];
    float* out = (float*)d_out;

    cudaFuncSetAttribute(flashm_kernel,
                         cudaFuncAttributeMaxDynamicSharedMemorySize, SMEM_TOTAL);

    // y = 0: K proj (BN fold).  y = 1..4: V proj 64-channel slabs.
    proj_kernel<<<dim3(HW / 64, 5, NB), 256>>>(
        x, Wk, bk, bn_gamma, bn_beta, bn_mean, bn_var, Wv, bv);
    flashm_kernel<<<dim3(HW / BQ, NB), 256, SMEM_TOTAL>>>(out);
}